// round 11
// baseline (speedup 1.0000x reference)
#include <cuda_runtime.h>
#include <cuda_bf16.h>
#include <math.h>
#include <stdint.h>

#define BATCH_N   4096
#define FEAT_D    512
#define NUM_AGES  100
#define AGE_PAD   128
#define EPS_F     1e-6f

#define TT 64                              // square tile edge for k_main
#define NT64 (BATCH_N / TT)                // 64
#define NPAIR (NT64 * (NT64 + 1) / 2)      // 2080 tiles I<=J
#define KC 64                              // K chunk (bf16) = 128B rows
#define NCHUNK (FEAT_D / KC)               // 8
#define NSTAGE 3

#define STAGE_MAIN 16384                   // Zi 8KB + Zj 8KB
#define STAGE_U    20480                   // Zi 4KB + Wa 16KB
#define META 2048
#define SMEM_MAIN (1024 + META + NSTAGE * STAGE_MAIN)   // ~52KB -> 4 CTAs/SM
#define SMEM_U    (1024 + NSTAGE * STAGE_U)

#define SW128(o) ((o) ^ (((o) >> 3) & 0x70))

// ---------------- device scratch ----------------
__device__ __nv_bfloat16 g_zb[BATCH_N * FEAT_D];    // age-sorted bf16 z
__device__ __nv_bfloat16 g_wab[AGE_PAD * FEAT_D];   // bf16 w per age (pad zero)
__device__ float  g_U[AGE_PAD * BATCH_N];           // U[a][i] = z_i . w_a
__device__ float  g_sq[BATCH_N];
__device__ int    g_ages[BATCH_N];                  // ascending
__device__ int    g_perm[BATCH_N];
__device__ double g_acc;
__device__ int    g_cnt;

// ---------------- PTX helpers ----------------
static __device__ __forceinline__ void ldsm_x4(uint32_t (&r)[4], uint32_t addr) {
    asm volatile("ldmatrix.sync.aligned.m8n8.x4.shared.b16 {%0,%1,%2,%3}, [%4];"
                 : "=r"(r[0]), "=r"(r[1]), "=r"(r[2]), "=r"(r[3]) : "r"(addr));
}
static __device__ __forceinline__ void mma_bf16(float (&c)[4], const uint32_t (&a)[4],
                                                const uint32_t b0, const uint32_t b1) {
    asm volatile(
        "mma.sync.aligned.m16n8k16.row.col.f32.bf16.bf16.f32 "
        "{%0,%1,%2,%3}, {%4,%5,%6,%7}, {%8,%9}, {%0,%1,%2,%3};"
        : "+f"(c[0]), "+f"(c[1]), "+f"(c[2]), "+f"(c[3])
        : "r"(a[0]), "r"(a[1]), "r"(a[2]), "r"(a[3]), "r"(b0), "r"(b1));
}
static __device__ __forceinline__ void cp16(uint32_t dst, const void* src) {
    asm volatile("cp.async.cg.shared.global [%0], [%1], 16;" :: "r"(dst), "l"(src) : "memory");
}

// ---------------- K0: block 0 = counting sort; blocks 1..16 = per-age w ----------------
__global__ __launch_bounds__(1024) void k_sort(const void* __restrict__ ages_raw,
                                               const float* __restrict__ proxies) {
    const int t = threadIdx.x;
    if (blockIdx.x > 0) {
        const int a  = (blockIdx.x - 1) * 8 + (t >> 7);
        const int tt = t & 127;
        if (a >= NUM_AGES) {
            if (a < AGE_PAD)
                ((uint2*)(g_wab + (size_t)a * FEAT_D))[tt] = make_uint2(0u, 0u);
            return;
        }
        const int an = min(a + 1, NUM_AGES - 1);
        const int ap = max(a - 1, 0);
        float4 c4 = ((const float4*)(proxies + (size_t)a  * FEAT_D))[tt];
        float4 n4 = ((const float4*)(proxies + (size_t)an * FEAT_D))[tt];
        float4 p4 = ((const float4*)(proxies + (size_t)ap * FEAT_D))[tt];
        float df[4] = {n4.x - c4.x, n4.y - c4.y, n4.z - c4.z, n4.w - c4.w};
        float db[4] = {p4.x - c4.x, p4.y - c4.y, p4.z - c4.z, p4.w - c4.w};

        float nf2 = 0.f, nb2 = 0.f;
#pragma unroll
        for (int q = 0; q < 4; ++q) { nf2 += df[q] * df[q]; nb2 += db[q] * db[q]; }
#pragma unroll
        for (int o = 16; o; o >>= 1) {
            nf2 += __shfl_xor_sync(0xFFFFFFFFu, nf2, o);
            nb2 += __shfl_xor_sync(0xFFFFFFFFu, nb2, o);
        }
        __shared__ float sf[32], sb[32];
        const int wg = t >> 5;
        if ((t & 31) == 0) { sf[wg] = nf2; sb[wg] = nb2; }
        __syncthreads();
        const int w0 = (t >> 7) * 4;
        nf2 = sf[w0] + sf[w0 + 1] + sf[w0 + 2] + sf[w0 + 3];
        nb2 = sb[w0] + sb[w0 + 1] + sb[w0 + 2] + sb[w0 + 3];
        const float rf = 1.f / (sqrtf(nf2) + EPS_F);
        const float rb = 1.f / (sqrtf(nb2) + EPS_F);

        __nv_bfloat162 w0v = __floats2bfloat162_rn(db[0] * rb - df[0] * rf,
                                                   db[1] * rb - df[1] * rf);
        __nv_bfloat162 w1v = __floats2bfloat162_rn(db[2] * rb - df[2] * rf,
                                                   db[3] * rb - df[3] * rf);
        uint2 u;
        u.x = *(uint32_t*)&w0v;
        u.y = *(uint32_t*)&w1v;
        ((uint2*)(g_wab + (size_t)a * FEAT_D))[tt] = u;
        return;
    }

    __shared__ int s_is64;
    __shared__ int s_hist[NUM_AGES];
    __shared__ int s_off[NUM_AGES];
    if (t == 0) {
        const long long* p = (const long long*)ages_raw;
        int ok = 1;
        for (int q = 0; q < 64; ++q) {
            long long v = p[q];
            if (v < 0 || v >= NUM_AGES) { ok = 0; break; }
        }
        s_is64 = ok;
        g_acc = 0.0;
        g_cnt = 0;
    }
    if (t < NUM_AGES) s_hist[t] = 0;
    __syncthreads();
    const int is64 = s_is64;

    for (int i = t; i < BATCH_N; i += 1024) {
        int a = is64 ? (int)((const long long*)ages_raw)[i]
                     : ((const int*)ages_raw)[i];
        atomicAdd(&s_hist[a], 1);
    }
    __syncthreads();
    if (t == 0) {
        int run = 0;
        for (int b = 0; b < NUM_AGES; ++b) { s_off[b] = run; run += s_hist[b]; }
    }
    __syncthreads();
    for (int i = t; i < BATCH_N; i += 1024) {
        int a = is64 ? (int)((const long long*)ages_raw)[i]
                     : ((const int*)ages_raw)[i];
        int pos = atomicAdd(&s_off[a], 1);
        g_perm[pos] = i;
        g_ages[pos] = a;
    }
}

// ---------------- K1: sorted z -> bf16, sq ----------------
__global__ __launch_bounds__(128) void k_prep(const float* __restrict__ z) {
    const int j    = blockIdx.x;
    const int t    = threadIdx.x;
    const int orig = g_perm[j];
    float4 z4 = ((const float4*)(z + (size_t)orig * FEAT_D))[t];

    __nv_bfloat162 p0 = __floats2bfloat162_rn(z4.x, z4.y);
    __nv_bfloat162 p1 = __floats2bfloat162_rn(z4.z, z4.w);
    uint2 u;
    u.x = *(uint32_t*)&p0;
    u.y = *(uint32_t*)&p1;
    ((uint2*)(g_zb + (size_t)j * FEAT_D))[t] = u;

    float sq = z4.x * z4.x + z4.y * z4.y + z4.z * z4.z + z4.w * z4.w;
#pragma unroll
    for (int o = 16; o; o >>= 1) sq += __shfl_xor_sync(0xFFFFFFFFu, sq, o);
    __shared__ float ss[4];
    if ((t & 31) == 0) ss[t >> 5] = sq;
    __syncthreads();
    if (t == 0) g_sq[j] = ss[0] + ss[1] + ss[2] + ss[3];
}

// -------- 3-stage pipeline core. 8 warps (2m x 4n).
// MTILES = m16-tiles per warp; NTILES = n8-tiles per warp (2 or 4).
#define PIPELINE_GEMM(MTILES, NTILES, SBYTES, AOFF)                                 \
    load_stage(0);                                                                  \
    load_stage(1);                                                                  \
    _Pragma("unroll 1")                                                             \
    for (int c = 0; c < NCHUNK; ++c) {                                              \
        if (c == NCHUNK - 1) asm volatile("cp.async.wait_group 0;" ::: "memory");   \
        else                 asm volatile("cp.async.wait_group 1;" ::: "memory");   \
        __syncthreads();                                                            \
        if (c + 2 < NCHUNK) load_stage(c + 2);                                      \
        const uint32_t st = stg0 + (uint32_t)(c % NSTAGE) * (SBYTES);               \
        const uint32_t zi = st, bj = st + (AOFF);                                   \
        _Pragma("unroll")                                                           \
        for (int kb = 0; kb < KC; kb += 16) {                                       \
            uint32_t a[MTILES][4];                                                  \
            _Pragma("unroll")                                                       \
            for (int mt = 0; mt < MTILES; ++mt) {                                   \
                int row = wm * (16 * MTILES) + mt * 16 + lr + (q8 & 1) * 8;         \
                int col = kb + (q8 >> 1) * 8;                                       \
                ldsm_x4(a[mt], zi + SW128((uint32_t)(row * 128 + col * 2)));        \
            }                                                                       \
            uint32_t bz[NTILES][2];                                                 \
            _Pragma("unroll")                                                       \
            for (int p = 0; p < NTILES / 2; ++p) {                                  \
                int row = wn * (8 * NTILES) + p * 16 + lr + (q8 >> 1) * 8;          \
                int col = kb + (q8 & 1) * 8;                                        \
                uint32_t rz[4];                                                     \
                ldsm_x4(rz, bj + SW128((uint32_t)(row * 128 + col * 2)));           \
                bz[2 * p][0] = rz[0]; bz[2 * p][1] = rz[1];                         \
                bz[2 * p + 1][0] = rz[2]; bz[2 * p + 1][1] = rz[3];                 \
            }                                                                       \
            _Pragma("unroll")                                                       \
            for (int mt = 0; mt < MTILES; ++mt)                                     \
                _Pragma("unroll")                                                   \
                for (int nt = 0; nt < NTILES; ++nt)                                 \
                    mma_bf16(cg[mt][nt], a[mt], bz[nt][0], bz[nt][1]);              \
        }                                                                           \
    }

// ---------------- K2a: U = Z . Wage^T  (128 CTAs, each 32 i-rows x 128 ages) -------
__global__ __launch_bounds__(256, 2) void k_u() {
    extern __shared__ char smem_raw[];
    uint32_t sbase;
    asm("{ .reg .u64 t; cvta.to.shared.u64 t, %1; cvt.u32.u64 %0, t; }"
        : "=r"(sbase) : "l"(smem_raw));
    const uint32_t stg0 = (sbase + 1023u) & ~1023u;

    const int i0   = blockIdx.x * 32;
    const int tid  = threadIdx.x;
    const int lane = tid & 31;
    const int wid  = tid >> 5;
    const int wm   = wid >> 2;
    const int wn   = wid & 3;
    const int q8 = lane >> 3;
    const int lr = lane & 7;

    auto load_stage = [&](int c) {
        uint32_t st = stg0 + (uint32_t)(c % NSTAGE) * STAGE_U;
        int k0 = c * KC;
        {
            int u = tid;
            int row = u >> 3, un = u & 7;
            cp16(st + SW128((uint32_t)(u * 16)),
                 g_zb + (size_t)(i0 + row) * FEAT_D + k0 + un * 8);
        }
#pragma unroll
        for (int q = 0; q < 4; ++q) {
            int u = tid + q * 256;
            int row = u >> 3, un = u & 7;
            cp16(st + 4096 + SW128((uint32_t)(u * 16)),
                 g_wab + (size_t)row * FEAT_D + k0 + un * 8);
        }
        asm volatile("cp.async.commit_group;" ::: "memory");
    };

    float cg[1][4][4] = {};
    PIPELINE_GEMM(1, 4, STAGE_U, 4096)

    const int g  = lane >> 2;
    const int tg = lane & 3;
    {
        int r0 = i0 + wm * 16 + g;
#pragma unroll
        for (int nt = 0; nt < 4; ++nt) {
            int a0 = wn * 32 + nt * 8 + tg * 2;
#pragma unroll
            for (int h = 0; h < 2; ++h) {
                g_U[(size_t)(a0 + h) * BATCH_N + r0]     = cg[0][nt][h];
                g_U[(size_t)(a0 + h) * BATCH_N + r0 + 8] = cg[0][nt][2 + h];
            }
        }
    }
}

// ---------------- K2b: 64x64 G tiles, 4 CTAs/SM, fused epilogue ----------------
__global__ __launch_bounds__(256, 4) void k_main(float* __restrict__ out) {
    extern __shared__ char smem_raw[];
    uint32_t sbase;
    asm("{ .reg .u64 t; cvta.to.shared.u64 t, %1; cvt.u32.u64 %0, t; }"
        : "=r"(sbase) : "l"(smem_raw));
    const uint32_t abase = (sbase + 1023u) & ~1023u;
    char* ab = smem_raw + (abase - sbase);
    const uint32_t stg0 = abase + META;

    float* s_sqi  = (float*)(ab);            // 64
    int*   s_agi  = (int*)(ab + 256);        // 64
    float* s_sqj  = (float*)(ab + 512);      // 64
    float* s_dwj  = (float*)(ab + 768);      // 64
    int*   s_agej = (int*)(ab + 1024);       // 64
    float* s_red  = (float*)(ab + META);     // reuses stage 0 after mainloop

    // linear block -> (I, J) with I <= J: cum(J) = J(J+1)/2
    int b = blockIdx.x;
    int J = (int)((sqrtf(8.0f * (float)b + 1.0f) - 1.0f) * 0.5f);
    while ((J + 1) * (J + 2) / 2 <= b) ++J;
    while (J * (J + 1) / 2 > b) --J;
    const int I  = b - J * (J + 1) / 2;
    const int i0 = I * TT;
    const int j0 = J * TT;

    const int tid  = threadIdx.x;
    const int lane = tid & 31;
    const int wid  = tid >> 5;
    const int wm   = wid >> 2;   // 0..1 (m offset 32)
    const int wn   = wid & 3;    // 0..3 (n offset 16)
    const int q8 = lane >> 3;
    const int lr = lane & 7;

    if (tid < 64) {
        int aj = g_ages[j0 + tid];
        s_agej[tid] = aj;
        s_sqj[tid]  = g_sq[j0 + tid];
        s_dwj[tid]  = g_U[(size_t)aj * BATCH_N + j0 + tid];
    } else if (tid < 128) {
        int r = tid - 64;
        s_sqi[r] = g_sq[i0 + r];
        s_agi[r] = g_ages[i0 + r];
    }

    auto load_stage = [&](int c) {
        uint32_t st = stg0 + (uint32_t)(c % NSTAGE) * STAGE_MAIN;
        int k0 = c * KC;
        {   // Zi: 512 units, 2 per thread
            int u = tid;
            int row = u >> 3, un = u & 7;
            cp16(st + SW128((uint32_t)(u * 16)),
                 g_zb + (size_t)(i0 + row) * FEAT_D + k0 + un * 8);
            u = tid + 256;
            row = u >> 3; un = u & 7;
            cp16(st + SW128((uint32_t)(u * 16)),
                 g_zb + (size_t)(i0 + row) * FEAT_D + k0 + un * 8);
        }
        {   // Zj: 512 units
            int u = tid;
            int row = u >> 3, un = u & 7;
            cp16(st + 8192 + SW128((uint32_t)(u * 16)),
                 g_zb + (size_t)(j0 + row) * FEAT_D + k0 + un * 8);
            u = tid + 256;
            row = u >> 3; un = u & 7;
            cp16(st + 8192 + SW128((uint32_t)(u * 16)),
                 g_zb + (size_t)(j0 + row) * FEAT_D + k0 + un * 8);
        }
        asm volatile("cp.async.commit_group;" ::: "memory");
    };

    float cg[2][2][4] = {};
    PIPELINE_GEMM(2, 2, STAGE_MAIN, 8192)

    // ---- epilogue: masked softplus; Gw from U[age_j][i] ----
    const int g  = lane >> 2;
    const int tg = lane & 3;
    float sqi0[2], sqi1[2];
    int   agi0[2], agi1[2];
#pragma unroll
    for (int mt = 0; mt < 2; ++mt) {
        int r0 = wm * 32 + mt * 16 + g;
        sqi0[mt] = s_sqi[r0];      agi0[mt] = s_agi[r0];
        sqi1[mt] = s_sqi[r0 + 8];  agi1[mt] = s_agi[r0 + 8];
    }

    float lsum = 0.f;
#pragma unroll
    for (int nt = 0; nt < 2; ++nt) {
#pragma unroll
        for (int h = 0; h < 2; ++h) {
            int cj = wn * 16 + nt * 8 + tg * 2 + h;
            int   agj = s_agej[cj];
            float sqj = s_sqj[cj], dwj = s_dwj[cj];
            const float* Up = g_U + (size_t)agj * BATCH_N + i0 + wm * 32 + g;
#pragma unroll
            for (int mt = 0; mt < 2; ++mt) {
                if (agi0[mt] < agj) {
                    float G  = cg[mt][nt][h];
                    float d2 = fmaxf(sqi0[mt] + sqj - 2.f * G, 0.f);
                    float x  = __fdividef((Up[mt * 16] - dwj) * 10.0f, sqrtf(d2) + EPS_F);
                    lsum += fmaxf(x, 0.f) + __logf(1.f + __expf(-fabsf(x)));
                }
                if (agi1[mt] < agj) {
                    float G  = cg[mt][nt][2 + h];
                    float d2 = fmaxf(sqi1[mt] + sqj - 2.f * G, 0.f);
                    float x  = __fdividef((Up[mt * 16 + 8] - dwj) * 10.0f, sqrtf(d2) + EPS_F);
                    lsum += fmaxf(x, 0.f) + __logf(1.f + __expf(-fabsf(x)));
                }
            }
        }
    }

    // s_red aliases stage memory: barrier so no warp is still reading tiles
    __syncthreads();
    s_red[tid] = lsum;
    __syncthreads();
#pragma unroll
    for (int s = 128; s > 0; s >>= 1) {
        if (tid < s) s_red[tid] += s_red[tid + s];
        __syncthreads();
    }
    if (tid == 0) {
        atomicAdd(&g_acc, (double)s_red[0]);
        __threadfence();
        int n = atomicAdd(&g_cnt, 1);
        if (n == NPAIR - 1) {
            __threadfence();
            double v = atomicAdd(&g_acc, 0.0);
            out[0] = (float)(v / ((double)BATCH_N * (double)(BATCH_N - 1)));
        }
    }
}

extern "C" void kernel_launch(void* const* d_in, const int* in_sizes, int n_in,
                              void* d_out, int out_size) {
    const float* z       = (const float*)d_in[0];
    const void*  ages    = d_in[1];
    const float* proxies = (const float*)d_in[2];
    float* out = (float*)d_out;

    cudaFuncSetAttribute(k_u,    cudaFuncAttributeMaxDynamicSharedMemorySize, SMEM_U);
    cudaFuncSetAttribute(k_main, cudaFuncAttributeMaxDynamicSharedMemorySize, SMEM_MAIN);

    k_sort<<<17, 1024>>>(ages, proxies);
    k_prep<<<BATCH_N, 128>>>(z);
    k_u<<<BATCH_N / 32, 256, SMEM_U>>>();
    k_main<<<NPAIR, 256, SMEM_MAIN>>>(out);
}

// round 12
// speedup vs baseline: 1.0684x; 1.0684x over previous
#include <cuda_runtime.h>
#include <cuda_bf16.h>
#include <math.h>
#include <stdint.h>

#define BATCH_N   4096
#define FEAT_D    512
#define NUM_AGES  100
#define AGE_PAD   128
#define EPS_F     1e-6f

#define TI 64
#define TJ 128
#define NJT (BATCH_N / TJ)                 // 32
#define NPAIR (NJT * NJT + NJT)            // 1056 main tiles
#define NU    (BATCH_N / 32)               // 128 U tiles
#define KC 64
#define NCHUNK (FEAT_D / KC)               // 8
#define NSTAGE 3

#define STAGE_MAIN 24576                   // Zi 8KB + Zj 16KB
#define STAGE_U    20480                   // Zi 4KB + Wa 16KB
#define META 2048
#define SMEM_MAIN (1024 + META + NSTAGE * STAGE_MAIN)   // 76800 -> 3 CTAs/SM

#define SW128(o) ((o) ^ (((o) >> 3) & 0x70))

// ---------------- device scratch ----------------
__device__ __nv_bfloat16 g_zb[BATCH_N * FEAT_D];
__device__ __nv_bfloat16 g_wab[AGE_PAD * FEAT_D];
__device__ float  g_U[AGE_PAD * BATCH_N];
__device__ float  g_sq[BATCH_N];
__device__ int    g_ages[BATCH_N];
__device__ int    g_perm[BATCH_N];
__device__ double g_acc;
__device__ int    g_cnt;
__device__ int    g_cnt_u;

// ---------------- PTX helpers ----------------
static __device__ __forceinline__ void ldsm_x4(uint32_t (&r)[4], uint32_t addr) {
    asm volatile("ldmatrix.sync.aligned.m8n8.x4.shared.b16 {%0,%1,%2,%3}, [%4];"
                 : "=r"(r[0]), "=r"(r[1]), "=r"(r[2]), "=r"(r[3]) : "r"(addr));
}
static __device__ __forceinline__ void mma_bf16(float (&c)[4], const uint32_t (&a)[4],
                                                const uint32_t b0, const uint32_t b1) {
    asm volatile(
        "mma.sync.aligned.m16n8k16.row.col.f32.bf16.bf16.f32 "
        "{%0,%1,%2,%3}, {%4,%5,%6,%7}, {%8,%9}, {%0,%1,%2,%3};"
        : "+f"(c[0]), "+f"(c[1]), "+f"(c[2]), "+f"(c[3])
        : "r"(a[0]), "r"(a[1]), "r"(a[2]), "r"(a[3]), "r"(b0), "r"(b1));
}
static __device__ __forceinline__ void cp16(uint32_t dst, const void* src) {
    asm volatile("cp.async.cg.shared.global [%0], [%1], 16;" :: "r"(dst), "l"(src) : "memory");
}

// ---------------- K0: block 0 = counting sort; blocks 1..16 = per-age w ----------------
__global__ __launch_bounds__(1024) void k_sort(const void* __restrict__ ages_raw,
                                               const float* __restrict__ proxies) {
    const int t = threadIdx.x;
    if (blockIdx.x > 0) {
        const int a  = (blockIdx.x - 1) * 8 + (t >> 7);
        const int tt = t & 127;
        if (a >= NUM_AGES) {
            if (a < AGE_PAD)
                ((uint2*)(g_wab + (size_t)a * FEAT_D))[tt] = make_uint2(0u, 0u);
            return;
        }
        const int an = min(a + 1, NUM_AGES - 1);
        const int ap = max(a - 1, 0);
        float4 c4 = ((const float4*)(proxies + (size_t)a  * FEAT_D))[tt];
        float4 n4 = ((const float4*)(proxies + (size_t)an * FEAT_D))[tt];
        float4 p4 = ((const float4*)(proxies + (size_t)ap * FEAT_D))[tt];
        float df[4] = {n4.x - c4.x, n4.y - c4.y, n4.z - c4.z, n4.w - c4.w};
        float db[4] = {p4.x - c4.x, p4.y - c4.y, p4.z - c4.z, p4.w - c4.w};

        float nf2 = 0.f, nb2 = 0.f;
#pragma unroll
        for (int q = 0; q < 4; ++q) { nf2 += df[q] * df[q]; nb2 += db[q] * db[q]; }
#pragma unroll
        for (int o = 16; o; o >>= 1) {
            nf2 += __shfl_xor_sync(0xFFFFFFFFu, nf2, o);
            nb2 += __shfl_xor_sync(0xFFFFFFFFu, nb2, o);
        }
        __shared__ float sf[32], sb[32];
        const int wg = t >> 5;
        if ((t & 31) == 0) { sf[wg] = nf2; sb[wg] = nb2; }
        __syncthreads();
        const int w0 = (t >> 7) * 4;
        nf2 = sf[w0] + sf[w0 + 1] + sf[w0 + 2] + sf[w0 + 3];
        nb2 = sb[w0] + sb[w0 + 1] + sb[w0 + 2] + sb[w0 + 3];
        const float rf = 1.f / (sqrtf(nf2) + EPS_F);
        const float rb = 1.f / (sqrtf(nb2) + EPS_F);

        __nv_bfloat162 w0v = __floats2bfloat162_rn(db[0] * rb - df[0] * rf,
                                                   db[1] * rb - df[1] * rf);
        __nv_bfloat162 w1v = __floats2bfloat162_rn(db[2] * rb - df[2] * rf,
                                                   db[3] * rb - df[3] * rf);
        uint2 u;
        u.x = *(uint32_t*)&w0v;
        u.y = *(uint32_t*)&w1v;
        ((uint2*)(g_wab + (size_t)a * FEAT_D))[tt] = u;
        return;
    }

    __shared__ int s_is64;
    __shared__ int s_hist[NUM_AGES];
    __shared__ int s_off[NUM_AGES];
    if (t == 0) {
        const long long* p = (const long long*)ages_raw;
        int ok = 1;
        for (int q = 0; q < 64; ++q) {
            long long v = p[q];
            if (v < 0 || v >= NUM_AGES) { ok = 0; break; }
        }
        s_is64 = ok;
        g_acc = 0.0;
        g_cnt = 0;
        g_cnt_u = 0;
    }
    if (t < NUM_AGES) s_hist[t] = 0;
    __syncthreads();
    const int is64 = s_is64;

    for (int i = t; i < BATCH_N; i += 1024) {
        int a = is64 ? (int)((const long long*)ages_raw)[i]
                     : ((const int*)ages_raw)[i];
        atomicAdd(&s_hist[a], 1);
    }
    __syncthreads();
    if (t == 0) {
        int run = 0;
        for (int b = 0; b < NUM_AGES; ++b) { s_off[b] = run; run += s_hist[b]; }
    }
    __syncthreads();
    for (int i = t; i < BATCH_N; i += 1024) {
        int a = is64 ? (int)((const long long*)ages_raw)[i]
                     : ((const int*)ages_raw)[i];
        int pos = atomicAdd(&s_off[a], 1);
        g_perm[pos] = i;
        g_ages[pos] = a;
    }
}

// ---------------- K1: sorted z -> bf16, sq ----------------
__global__ __launch_bounds__(128) void k_prep(const float* __restrict__ z) {
    const int j    = blockIdx.x;
    const int t    = threadIdx.x;
    const int orig = g_perm[j];
    float4 z4 = ((const float4*)(z + (size_t)orig * FEAT_D))[t];

    __nv_bfloat162 p0 = __floats2bfloat162_rn(z4.x, z4.y);
    __nv_bfloat162 p1 = __floats2bfloat162_rn(z4.z, z4.w);
    uint2 u;
    u.x = *(uint32_t*)&p0;
    u.y = *(uint32_t*)&p1;
    ((uint2*)(g_zb + (size_t)j * FEAT_D))[t] = u;

    float sq = z4.x * z4.x + z4.y * z4.y + z4.z * z4.z + z4.w * z4.w;
#pragma unroll
    for (int o = 16; o; o >>= 1) sq += __shfl_xor_sync(0xFFFFFFFFu, sq, o);
    __shared__ float ss[4];
    if ((t & 31) == 0) ss[t >> 5] = sq;
    __syncthreads();
    if (t == 0) g_sq[j] = ss[0] + ss[1] + ss[2] + ss[3];
}

// -------- 3-stage pipeline core: 8 warps (2m x 4n), prefetch depth 2 --------
#define PIPELINE_GEMM(MTILES, SBYTES, AOFF)                                         \
    load_stage(0);                                                                  \
    load_stage(1);                                                                  \
    _Pragma("unroll 1")                                                             \
    for (int c = 0; c < NCHUNK; ++c) {                                              \
        if (c == NCHUNK - 1) asm volatile("cp.async.wait_group 0;" ::: "memory");   \
        else                 asm volatile("cp.async.wait_group 1;" ::: "memory");   \
        __syncthreads();                                                            \
        if (c + 2 < NCHUNK) load_stage(c + 2);                                      \
        const uint32_t st = stg0 + (uint32_t)(c % NSTAGE) * (SBYTES);               \
        const uint32_t zi = st, bj = st + (AOFF);                                   \
        _Pragma("unroll")                                                           \
        for (int kb = 0; kb < KC; kb += 16) {                                       \
            uint32_t a[MTILES][4];                                                  \
            _Pragma("unroll")                                                       \
            for (int mt = 0; mt < MTILES; ++mt) {                                   \
                int row = wm * (16 * MTILES) + mt * 16 + lr + (q8 & 1) * 8;         \
                int col = kb + (q8 >> 1) * 8;                                       \
                ldsm_x4(a[mt], zi + SW128((uint32_t)(row * 128 + col * 2)));        \
            }                                                                       \
            uint32_t bz[4][2];                                                      \
            _Pragma("unroll")                                                       \
            for (int p = 0; p < 2; ++p) {                                           \
                int row = wn * 32 + p * 16 + lr + (q8 >> 1) * 8;                    \
                int col = kb + (q8 & 1) * 8;                                        \
                uint32_t rz[4];                                                     \
                ldsm_x4(rz, bj + SW128((uint32_t)(row * 128 + col * 2)));           \
                bz[2 * p][0] = rz[0]; bz[2 * p][1] = rz[1];                         \
                bz[2 * p + 1][0] = rz[2]; bz[2 * p + 1][1] = rz[3];                 \
            }                                                                       \
            _Pragma("unroll")                                                       \
            for (int mt = 0; mt < MTILES; ++mt)                                     \
                _Pragma("unroll")                                                   \
                for (int nt = 0; nt < 4; ++nt)                                      \
                    mma_bf16(cg[mt][nt], a[mt], bz[nt][0], bz[nt][1]);              \
        }                                                                           \
    }

// ---------------- fused K2: blocks 0..NU-1 compute U; the rest do G tiles ----------------
__global__ __launch_bounds__(256, 3) void k_main(float* __restrict__ out) {
    extern __shared__ char smem_raw[];
    uint32_t sbase;
    asm("{ .reg .u64 t; cvta.to.shared.u64 t, %1; cvt.u32.u64 %0, t; }"
        : "=r"(sbase) : "l"(smem_raw));
    const uint32_t abase = (sbase + 1023u) & ~1023u;
    char* ab = smem_raw + (abase - sbase);
    const uint32_t stg0 = abase + META;

    const int tid  = threadIdx.x;
    const int lane = tid & 31;
    const int wid  = tid >> 5;
    const int wm   = wid >> 2;
    const int wn   = wid & 3;
    const int q8 = lane >> 3;
    const int lr = lane & 7;

    if (blockIdx.x < NU) {
        // ---------- U tile: 32 i-rows x 128 ages ----------
        const int i0 = blockIdx.x * 32;

        auto load_stage = [&](int c) {
            uint32_t st = stg0 + (uint32_t)(c % NSTAGE) * STAGE_U;
            int k0 = c * KC;
            {
                int u = tid;
                int row = u >> 3, un = u & 7;
                cp16(st + SW128((uint32_t)(u * 16)),
                     g_zb + (size_t)(i0 + row) * FEAT_D + k0 + un * 8);
            }
#pragma unroll
            for (int q = 0; q < 4; ++q) {
                int u = tid + q * 256;
                int row = u >> 3, un = u & 7;
                cp16(st + 4096 + SW128((uint32_t)(u * 16)),
                     g_wab + (size_t)row * FEAT_D + k0 + un * 8);
            }
            asm volatile("cp.async.commit_group;" ::: "memory");
        };

        float cg[1][4][4] = {};
        PIPELINE_GEMM(1, STAGE_U, 4096)

        const int g  = lane >> 2;
        const int tg = lane & 3;
        {
            int r0 = i0 + wm * 16 + g;
#pragma unroll
            for (int nt = 0; nt < 4; ++nt) {
                int a0 = wn * 32 + nt * 8 + tg * 2;
#pragma unroll
                for (int h = 0; h < 2; ++h) {
                    g_U[(size_t)(a0 + h) * BATCH_N + r0]     = cg[0][nt][h];
                    g_U[(size_t)(a0 + h) * BATCH_N + r0 + 8] = cg[0][nt][2 + h];
                }
            }
        }
        __syncthreads();
        if (tid == 0) {
            __threadfence();
            atomicAdd(&g_cnt_u, 1);
        }
        return;
    }

    // ---------- main tile: 64 x 128 G + fused epilogue ----------
    float* s_sqi  = (float*)(ab);
    int*   s_agi  = (int*)(ab + 256);
    float* s_sqj  = (float*)(ab + 512);
    float* s_dwj  = (float*)(ab + 1024);
    int*   s_agej = (int*)(ab + 1536);
    float* s_red  = (float*)(ab + META);     // reuses stage memory post-mainloop

    int b = blockIdx.x - NU;
    int J = (int)((sqrtf(4.0f * (float)b + 1.0f) - 1.0f) * 0.5f);
    while ((J + 1) * (J + 1) + (J + 1) <= b) ++J;
    while (J * J + J > b) --J;
    const int I  = b - (J * J + J);
    const int i0 = I * TI;
    const int j0 = J * TJ;

    if (tid < 128) {
        int aj = g_ages[j0 + tid];
        s_agej[tid] = aj;
        s_sqj[tid]  = g_sq[j0 + tid];
    } else if (tid < 192) {
        int r = tid - 128;
        s_sqi[r] = g_sq[i0 + r];
        s_agi[r] = g_ages[i0 + r];
    }

    auto load_stage = [&](int c) {
        uint32_t st = stg0 + (uint32_t)(c % NSTAGE) * STAGE_MAIN;
        int k0 = c * KC;
#pragma unroll
        for (int q = 0; q < 2; ++q) {
            int u = tid + q * 256;
            int row = u >> 3, un = u & 7;
            cp16(st + SW128((uint32_t)(u * 16)),
                 g_zb + (size_t)(i0 + row) * FEAT_D + k0 + un * 8);
        }
#pragma unroll
        for (int q = 0; q < 4; ++q) {
            int u = tid + q * 256;
            int row = u >> 3, un = u & 7;
            cp16(st + 8192 + SW128((uint32_t)(u * 16)),
                 g_zb + (size_t)(j0 + row) * FEAT_D + k0 + un * 8);
        }
        asm volatile("cp.async.commit_group;" ::: "memory");
    };

    float cg[2][4][4] = {};
    PIPELINE_GEMM(2, STAGE_MAIN, 8192)

    // ---- gate on U completion (U blocks are wave-1, long since done) ----
    if (tid == 0) {
        while (*(volatile int*)&g_cnt_u < NU) {}
    }
    __syncthreads();
    if (tid < 128) {
        s_dwj[tid] = g_U[(size_t)s_agej[tid] * BATCH_N + j0 + tid];
    }
    __syncthreads();

    // ---- epilogue: masked softplus; Gw from U[age_j][i] ----
    const int g  = lane >> 2;
    const int tg = lane & 3;
    float sqi0[2], sqi1[2];
    int   agi0[2], agi1[2];
#pragma unroll
    for (int mt = 0; mt < 2; ++mt) {
        int r0 = wm * 32 + mt * 16 + g;
        sqi0[mt] = s_sqi[r0];      agi0[mt] = s_agi[r0];
        sqi1[mt] = s_sqi[r0 + 8];  agi1[mt] = s_agi[r0 + 8];
    }

    float lsum = 0.f;
#pragma unroll
    for (int nt = 0; nt < 4; ++nt) {
#pragma unroll
        for (int h = 0; h < 2; ++h) {
            int cj = wn * 32 + nt * 8 + tg * 2 + h;
            int   agj = s_agej[cj];
            float sqj = s_sqj[cj], dwj = s_dwj[cj];
            const float* Up = g_U + (size_t)agj * BATCH_N + i0 + wm * 32 + g;
#pragma unroll
            for (int mt = 0; mt < 2; ++mt) {
                if (agi0[mt] < agj) {
                    float G  = cg[mt][nt][h];
                    float d2 = fmaxf(sqi0[mt] + sqj - 2.f * G, 0.f);
                    float x  = __fdividef((Up[mt * 16] - dwj) * 10.0f, sqrtf(d2) + EPS_F);
                    lsum += fmaxf(x, 0.f) + __logf(1.f + __expf(-fabsf(x)));
                }
                if (agi1[mt] < agj) {
                    float G  = cg[mt][nt][2 + h];
                    float d2 = fmaxf(sqi1[mt] + sqj - 2.f * G, 0.f);
                    float x  = __fdividef((Up[mt * 16 + 8] - dwj) * 10.0f, sqrtf(d2) + EPS_F);
                    lsum += fmaxf(x, 0.f) + __logf(1.f + __expf(-fabsf(x)));
                }
            }
        }
    }

    __syncthreads();           // s_red aliases stage memory
    s_red[tid] = lsum;
    __syncthreads();
#pragma unroll
    for (int s = 128; s > 0; s >>= 1) {
        if (tid < s) s_red[tid] += s_red[tid + s];
        __syncthreads();
    }
    if (tid == 0) {
        atomicAdd(&g_acc, (double)s_red[0]);
        __threadfence();
        int n = atomicAdd(&g_cnt, 1);
        if (n == NPAIR - 1) {
            __threadfence();
            double v = atomicAdd(&g_acc, 0.0);
            out[0] = (float)(v / ((double)BATCH_N * (double)(BATCH_N - 1)));
        }
    }
}

extern "C" void kernel_launch(void* const* d_in, const int* in_sizes, int n_in,
                              void* d_out, int out_size) {
    const float* z       = (const float*)d_in[0];
    const void*  ages    = d_in[1];
    const float* proxies = (const float*)d_in[2];
    float* out = (float*)d_out;

    cudaFuncSetAttribute(k_main, cudaFuncAttributeMaxDynamicSharedMemorySize, SMEM_MAIN);

    k_sort<<<17, 1024>>>(ages, proxies);
    k_prep<<<BATCH_N, 128>>>(z);
    k_main<<<NU + NPAIR, 256, SMEM_MAIN>>>(out);
}

// round 13
// speedup vs baseline: 1.0759x; 1.0070x over previous
#include <cuda_runtime.h>
#include <cuda_bf16.h>
#include <math.h>
#include <stdint.h>

#define BATCH_N   4096
#define FEAT_D    512
#define NUM_AGES  100
#define AGE_PAD   128
#define EPS_F     1e-6f

#define TI 64
#define TJ 128
#define NJT (BATCH_N / TJ)                 // 32
#define NPAIR (NJT * NJT + NJT)            // 1056 main tiles
#define NU    (BATCH_N / 32)               // 128 U tiles
#define KC 64
#define NCHUNK (FEAT_D / KC)               // 8
#define NSTAGE 3

#define STAGE_MAIN 24576                   // Zi 8KB + Zj 16KB
#define STAGE_U    20480                   // Zi 4KB + Wa 16KB
#define META 2048
#define SMEM_MAIN (1024 + META + NSTAGE * STAGE_MAIN)   // 76800 -> 3 CTAs/SM

#define SW128(o) ((o) ^ (((o) >> 3) & 0x70))

// ---------------- device scratch ----------------
__device__ __nv_bfloat16 g_zb[BATCH_N * FEAT_D];
__device__ __nv_bfloat16 g_wab[AGE_PAD * FEAT_D];
__device__ float  g_U[AGE_PAD * BATCH_N];
__device__ float  g_sq[BATCH_N];
__device__ int    g_ages[BATCH_N];
__device__ int    g_perm[BATCH_N];
__device__ double g_acc;
__device__ int    g_cnt;
__device__ int    g_cnt_u;

// ---------------- PTX helpers ----------------
static __device__ __forceinline__ void ldsm_x4(uint32_t (&r)[4], uint32_t addr) {
    asm volatile("ldmatrix.sync.aligned.m8n8.x4.shared.b16 {%0,%1,%2,%3}, [%4];"
                 : "=r"(r[0]), "=r"(r[1]), "=r"(r[2]), "=r"(r[3]) : "r"(addr));
}
static __device__ __forceinline__ void mma_bf16(float (&c)[4], const uint32_t (&a)[4],
                                                const uint32_t b0, const uint32_t b1) {
    asm volatile(
        "mma.sync.aligned.m16n8k16.row.col.f32.bf16.bf16.f32 "
        "{%0,%1,%2,%3}, {%4,%5,%6,%7}, {%8,%9}, {%0,%1,%2,%3};"
        : "+f"(c[0]), "+f"(c[1]), "+f"(c[2]), "+f"(c[3])
        : "r"(a[0]), "r"(a[1]), "r"(a[2]), "r"(a[3]), "r"(b0), "r"(b1));
}
static __device__ __forceinline__ void cp16(uint32_t dst, const void* src) {
    asm volatile("cp.async.cg.shared.global [%0], [%1], 16;" :: "r"(dst), "l"(src) : "memory");
}

// ---- parallel int64/int32 autodetect: 64 lanes (2 warps) + ballot ----
static __device__ __forceinline__ int detect_is64(const void* ages_raw, int t) {
    // t in [0,64): read value t as int64; if buffer is int32, hi words make
    // values out of [0, NUM_AGES) with overwhelming probability.
    long long v = ((const long long*)ages_raw)[t];
    int ok = (v >= 0 && v < NUM_AGES) ? 1 : 0;
    unsigned m = __ballot_sync(0xFFFFFFFFu, ok);
    return m == 0xFFFFFFFFu ? 1 : 0;   // combined across both warps via shared below
}

// ---------------- K0: block 0 = counting sort; blocks 1..16 = per-age w ----------------
__global__ __launch_bounds__(1024) void k_sort(const void* __restrict__ ages_raw,
                                               const float* __restrict__ proxies) {
    const int t = threadIdx.x;
    if (blockIdx.x > 0) {
        const int a  = (blockIdx.x - 1) * 8 + (t >> 7);
        const int tt = t & 127;
        if (a >= NUM_AGES) {
            if (a < AGE_PAD)
                ((uint2*)(g_wab + (size_t)a * FEAT_D))[tt] = make_uint2(0u, 0u);
            return;
        }
        const int an = min(a + 1, NUM_AGES - 1);
        const int ap = max(a - 1, 0);
        float4 c4 = ((const float4*)(proxies + (size_t)a  * FEAT_D))[tt];
        float4 n4 = ((const float4*)(proxies + (size_t)an * FEAT_D))[tt];
        float4 p4 = ((const float4*)(proxies + (size_t)ap * FEAT_D))[tt];
        float df[4] = {n4.x - c4.x, n4.y - c4.y, n4.z - c4.z, n4.w - c4.w};
        float db[4] = {p4.x - c4.x, p4.y - c4.y, p4.z - c4.z, p4.w - c4.w};

        float nf2 = 0.f, nb2 = 0.f;
#pragma unroll
        for (int q = 0; q < 4; ++q) { nf2 += df[q] * df[q]; nb2 += db[q] * db[q]; }
#pragma unroll
        for (int o = 16; o; o >>= 1) {
            nf2 += __shfl_xor_sync(0xFFFFFFFFu, nf2, o);
            nb2 += __shfl_xor_sync(0xFFFFFFFFu, nb2, o);
        }
        __shared__ float sf[32], sb[32];
        const int wg = t >> 5;
        if ((t & 31) == 0) { sf[wg] = nf2; sb[wg] = nb2; }
        __syncthreads();
        const int w0 = (t >> 7) * 4;
        nf2 = sf[w0] + sf[w0 + 1] + sf[w0 + 2] + sf[w0 + 3];
        nb2 = sb[w0] + sb[w0 + 1] + sb[w0 + 2] + sb[w0 + 3];
        const float rf = 1.f / (sqrtf(nf2) + EPS_F);
        const float rb = 1.f / (sqrtf(nb2) + EPS_F);

        __nv_bfloat162 w0v = __floats2bfloat162_rn(db[0] * rb - df[0] * rf,
                                                   db[1] * rb - df[1] * rf);
        __nv_bfloat162 w1v = __floats2bfloat162_rn(db[2] * rb - df[2] * rf,
                                                   db[3] * rb - df[3] * rf);
        uint2 u;
        u.x = *(uint32_t*)&w0v;
        u.y = *(uint32_t*)&w1v;
        ((uint2*)(g_wab + (size_t)a * FEAT_D))[tt] = u;
        return;
    }

    __shared__ int s_ok[2];
    __shared__ int s_is64;
    __shared__ int s_hist[NUM_AGES];
    __shared__ int s_off[NUM_AGES];
    if (t < 64) {
        int ok = detect_is64(ages_raw, t);
        if ((t & 31) == 0) s_ok[t >> 5] = ok;
    }
    if (t == 0) {
        g_acc = 0.0;
        g_cnt = 0;
        g_cnt_u = 0;
    }
    if (t < NUM_AGES) s_hist[t] = 0;
    __syncthreads();
    if (t == 0) s_is64 = s_ok[0] & s_ok[1];
    __syncthreads();
    const int is64 = s_is64;

    for (int i = t; i < BATCH_N; i += 1024) {
        int a = is64 ? (int)((const long long*)ages_raw)[i]
                     : ((const int*)ages_raw)[i];
        atomicAdd(&s_hist[a], 1);
    }
    __syncthreads();
    if (t == 0) {
        int run = 0;
        for (int b = 0; b < NUM_AGES; ++b) { s_off[b] = run; run += s_hist[b]; }
    }
    __syncthreads();
    for (int i = t; i < BATCH_N; i += 1024) {
        int a = is64 ? (int)((const long long*)ages_raw)[i]
                     : ((const int*)ages_raw)[i];
        int pos = atomicAdd(&s_off[a], 1);
        g_perm[pos] = i;
        g_ages[pos] = a;
    }
}

// ---------------- K1: sorted z -> bf16, sq  (512 blocks x 256 thr, 8 rows each) ---------
__global__ __launch_bounds__(256) void k_prep(const float* __restrict__ z) {
    const int r  = threadIdx.x >> 5;                   // row-slot 0..7
    const int l  = threadIdx.x & 31;                   // lane: 4 floats each over 128
    const int j  = blockIdx.x * 8 + r;
    const int orig = g_perm[j];
    float4 z4a = ((const float4*)(z + (size_t)orig * FEAT_D))[l];
    float4 z4b = ((const float4*)(z + (size_t)orig * FEAT_D))[l + 32];
    float4 z4c = ((const float4*)(z + (size_t)orig * FEAT_D))[l + 64];
    float4 z4d = ((const float4*)(z + (size_t)orig * FEAT_D))[l + 96];

    uint2* dst = (uint2*)(g_zb + (size_t)j * FEAT_D);
    float sq = 0.f;
    float4 vv[4] = {z4a, z4b, z4c, z4d};
#pragma unroll
    for (int q = 0; q < 4; ++q) {
        float4 v = vv[q];
        __nv_bfloat162 p0 = __floats2bfloat162_rn(v.x, v.y);
        __nv_bfloat162 p1 = __floats2bfloat162_rn(v.z, v.w);
        uint2 u;
        u.x = *(uint32_t*)&p0;
        u.y = *(uint32_t*)&p1;
        dst[l + q * 32] = u;
        sq += v.x * v.x + v.y * v.y + v.z * v.z + v.w * v.w;
    }
#pragma unroll
    for (int o = 16; o; o >>= 1) sq += __shfl_xor_sync(0xFFFFFFFFu, sq, o);
    if (l == 0) g_sq[j] = sq;
}

// -------- 3-stage pipeline core: 8 warps (2m x 4n), prefetch depth 2 --------
#define PIPELINE_GEMM(MTILES, SBYTES, AOFF)                                         \
    load_stage(0);                                                                  \
    load_stage(1);                                                                  \
    _Pragma("unroll 1")                                                             \
    for (int c = 0; c < NCHUNK; ++c) {                                              \
        if (c == NCHUNK - 1) asm volatile("cp.async.wait_group 0;" ::: "memory");   \
        else                 asm volatile("cp.async.wait_group 1;" ::: "memory");   \
        __syncthreads();                                                            \
        if (c + 2 < NCHUNK) load_stage(c + 2);                                      \
        const uint32_t st = stg0 + (uint32_t)(c % NSTAGE) * (SBYTES);               \
        const uint32_t zi = st, bj = st + (AOFF);                                   \
        _Pragma("unroll")                                                           \
        for (int kb = 0; kb < KC; kb += 16) {                                       \
            uint32_t a[MTILES][4];                                                  \
            _Pragma("unroll")                                                       \
            for (int mt = 0; mt < MTILES; ++mt) {                                   \
                int row = wm * (16 * MTILES) + mt * 16 + lr + (q8 & 1) * 8;         \
                int col = kb + (q8 >> 1) * 8;                                       \
                ldsm_x4(a[mt], zi + SW128((uint32_t)(row * 128 + col * 2)));        \
            }                                                                       \
            uint32_t bz[4][2];                                                      \
            _Pragma("unroll")                                                       \
            for (int p = 0; p < 2; ++p) {                                           \
                int row = wn * 32 + p * 16 + lr + (q8 >> 1) * 8;                    \
                int col = kb + (q8 & 1) * 8;                                        \
                uint32_t rz[4];                                                     \
                ldsm_x4(rz, bj + SW128((uint32_t)(row * 128 + col * 2)));           \
                bz[2 * p][0] = rz[0]; bz[2 * p][1] = rz[1];                         \
                bz[2 * p + 1][0] = rz[2]; bz[2 * p + 1][1] = rz[3];                 \
            }                                                                       \
            _Pragma("unroll")                                                       \
            for (int mt = 0; mt < MTILES; ++mt)                                     \
                _Pragma("unroll")                                                   \
                for (int nt = 0; nt < 4; ++nt)                                      \
                    mma_bf16(cg[mt][nt], a[mt], bz[nt][0], bz[nt][1]);              \
        }                                                                           \
    }

// ---------------- fused K2: blocks 0..NU-1 compute U; the rest do G tiles ----------------
__global__ __launch_bounds__(256, 3) void k_main(float* __restrict__ out) {
    extern __shared__ char smem_raw[];
    uint32_t sbase;
    asm("{ .reg .u64 t; cvta.to.shared.u64 t, %1; cvt.u32.u64 %0, t; }"
        : "=r"(sbase) : "l"(smem_raw));
    const uint32_t abase = (sbase + 1023u) & ~1023u;
    char* ab = smem_raw + (abase - sbase);
    const uint32_t stg0 = abase + META;

    const int tid  = threadIdx.x;
    const int lane = tid & 31;
    const int wid  = tid >> 5;
    const int wm   = wid >> 2;
    const int wn   = wid & 3;
    const int q8 = lane >> 3;
    const int lr = lane & 7;

    if (blockIdx.x < NU) {
        const int i0 = blockIdx.x * 32;

        auto load_stage = [&](int c) {
            uint32_t st = stg0 + (uint32_t)(c % NSTAGE) * STAGE_U;
            int k0 = c * KC;
            {
                int u = tid;
                int row = u >> 3, un = u & 7;
                cp16(st + SW128((uint32_t)(u * 16)),
                     g_zb + (size_t)(i0 + row) * FEAT_D + k0 + un * 8);
            }
#pragma unroll
            for (int q = 0; q < 4; ++q) {
                int u = tid + q * 256;
                int row = u >> 3, un = u & 7;
                cp16(st + 4096 + SW128((uint32_t)(u * 16)),
                     g_wab + (size_t)row * FEAT_D + k0 + un * 8);
            }
            asm volatile("cp.async.commit_group;" ::: "memory");
        };

        float cg[1][4][4] = {};
        PIPELINE_GEMM(1, STAGE_U, 4096)

        const int g  = lane >> 2;
        const int tg = lane & 3;
        {
            int r0 = i0 + wm * 16 + g;
#pragma unroll
            for (int nt = 0; nt < 4; ++nt) {
                int a0 = wn * 32 + nt * 8 + tg * 2;
#pragma unroll
                for (int h = 0; h < 2; ++h) {
                    g_U[(size_t)(a0 + h) * BATCH_N + r0]     = cg[0][nt][h];
                    g_U[(size_t)(a0 + h) * BATCH_N + r0 + 8] = cg[0][nt][2 + h];
                }
            }
        }
        __syncthreads();
        if (tid == 0) {
            __threadfence();
            atomicAdd(&g_cnt_u, 1);
        }
        return;
    }

    // ---------- main tile: 64 x 128 G + fused epilogue ----------
    float* s_sqi  = (float*)(ab);
    int*   s_agi  = (int*)(ab + 256);
    float* s_sqj  = (float*)(ab + 512);
    float* s_dwj  = (float*)(ab + 1024);
    int*   s_agej = (int*)(ab + 1536);
    float* s_red  = (float*)(ab + META);

    int b = blockIdx.x - NU;
    int J = (int)((sqrtf(4.0f * (float)b + 1.0f) - 1.0f) * 0.5f);
    while ((J + 1) * (J + 1) + (J + 1) <= b) ++J;
    while (J * J + J > b) --J;
    const int I  = b - (J * J + J);
    const int i0 = I * TI;
    const int j0 = J * TJ;

    if (tid < 128) {
        int aj = g_ages[j0 + tid];
        s_agej[tid] = aj;
        s_sqj[tid]  = g_sq[j0 + tid];
    } else if (tid < 192) {
        int r = tid - 128;
        s_sqi[r] = g_sq[i0 + r];
        s_agi[r] = g_ages[i0 + r];
    }

    auto load_stage = [&](int c) {
        uint32_t st = stg0 + (uint32_t)(c % NSTAGE) * STAGE_MAIN;
        int k0 = c * KC;
#pragma unroll
        for (int q = 0; q < 2; ++q) {
            int u = tid + q * 256;
            int row = u >> 3, un = u & 7;
            cp16(st + SW128((uint32_t)(u * 16)),
                 g_zb + (size_t)(i0 + row) * FEAT_D + k0 + un * 8);
        }
#pragma unroll
        for (int q = 0; q < 4; ++q) {
            int u = tid + q * 256;
            int row = u >> 3, un = u & 7;
            cp16(st + 8192 + SW128((uint32_t)(u * 16)),
                 g_zb + (size_t)(j0 + row) * FEAT_D + k0 + un * 8);
        }
        asm volatile("cp.async.commit_group;" ::: "memory");
    };

    float cg[2][4][4] = {};
    PIPELINE_GEMM(2, STAGE_MAIN, 8192)

    // ---- gate on U completion ----
    if (tid == 0) {
        while (*(volatile int*)&g_cnt_u < NU) {}
    }
    __syncthreads();
    if (tid < 128) {
        s_dwj[tid] = g_U[(size_t)s_agej[tid] * BATCH_N + j0 + tid];
    }
    __syncthreads();

    // ---- epilogue ----
    const int g  = lane >> 2;
    const int tg = lane & 3;
    float sqi0[2], sqi1[2];
    int   agi0[2], agi1[2];
#pragma unroll
    for (int mt = 0; mt < 2; ++mt) {
        int r0 = wm * 32 + mt * 16 + g;
        sqi0[mt] = s_sqi[r0];      agi0[mt] = s_agi[r0];
        sqi1[mt] = s_sqi[r0 + 8];  agi1[mt] = s_agi[r0 + 8];
    }

    float lsum = 0.f;
#pragma unroll
    for (int nt = 0; nt < 4; ++nt) {
#pragma unroll
        for (int h = 0; h < 2; ++h) {
            int cj = wn * 32 + nt * 8 + tg * 2 + h;
            int   agj = s_agej[cj];
            float sqj = s_sqj[cj], dwj = s_dwj[cj];
            const float* Up = g_U + (size_t)agj * BATCH_N + i0 + wm * 32 + g;
#pragma unroll
            for (int mt = 0; mt < 2; ++mt) {
                if (agi0[mt] < agj) {
                    float G  = cg[mt][nt][h];
                    float d2 = fmaxf(sqi0[mt] + sqj - 2.f * G, 0.f);
                    float x  = __fdividef((Up[mt * 16] - dwj) * 10.0f, sqrtf(d2) + EPS_F);
                    lsum += fmaxf(x, 0.f) + __logf(1.f + __expf(-fabsf(x)));
                }
                if (agi1[mt] < agj) {
                    float G  = cg[mt][nt][2 + h];
                    float d2 = fmaxf(sqi1[mt] + sqj - 2.f * G, 0.f);
                    float x  = __fdividef((Up[mt * 16 + 8] - dwj) * 10.0f, sqrtf(d2) + EPS_F);
                    lsum += fmaxf(x, 0.f) + __logf(1.f + __expf(-fabsf(x)));
                }
            }
        }
    }

    __syncthreads();
    s_red[tid] = lsum;
    __syncthreads();
#pragma unroll
    for (int s = 128; s > 0; s >>= 1) {
        if (tid < s) s_red[tid] += s_red[tid + s];
        __syncthreads();
    }
    if (tid == 0) {
        atomicAdd(&g_acc, (double)s_red[0]);
        __threadfence();
        int n = atomicAdd(&g_cnt, 1);
        if (n == NPAIR - 1) {
            __threadfence();
            double v = atomicAdd(&g_acc, 0.0);
            out[0] = (float)(v / ((double)BATCH_N * (double)(BATCH_N - 1)));
        }
    }
}

extern "C" void kernel_launch(void* const* d_in, const int* in_sizes, int n_in,
                              void* d_out, int out_size) {
    const float* z       = (const float*)d_in[0];
    const void*  ages    = d_in[1];
    const float* proxies = (const float*)d_in[2];
    float* out = (float*)d_out;

    cudaFuncSetAttribute(k_main, cudaFuncAttributeMaxDynamicSharedMemorySize, SMEM_MAIN);

    k_sort<<<17, 1024>>>(ages, proxies);
    k_prep<<<BATCH_N / 8, 256>>>(z);
    k_main<<<NU + NPAIR, 256, SMEM_MAIN>>>(out);
}